// round 9
// baseline (speedup 1.0000x reference)
#include <cuda_runtime.h>
#include <math.h>

// DCN collapsed-affine, round 9:
//  - k_a: fused v3+v2 (each block recomputes v3, writes a complete v2 chunk;
//         block 0 seeds g_r with pred_b + d2.v3 + d3.pw_h, zeroes g_u)
//  - k_u: reads full v2, atomicAdds u and r contributions
//  - k_main: 256 thr, 2 rows/warp, float2, grid 256, launch_bounds(256,4),
//    depth-5 dual-row prefetch. LDS/row halved vs R7 at 50% occupancy.

#define EPSF 1e-5f

constexpr int Bn   = 4096;
constexpr int Fn   = 26;
constexpr int Vn   = 10000;
constexpr int Dn   = 64;
constexpr int D0   = 1664;   // Fn*Dn
constexpr int NUMB = 13;
constexpr int INW  = 1677;   // D0 + NUMB
constexpr int H1   = 1024;
constexpr int H2   = 512;
constexpr int H3   = 256;

// Scratch (device globals)
__device__ float g_v2[H1];        // full v2
__device__ float g_u[1792];       // u (atomic-accumulated; zeroed in k_a)
__device__ float g_r;             // scalar r (seeded in k_a, atomics in k_u)

__device__ __forceinline__ float warp_sum(float v) {
    #pragma unroll
    for (int o = 16; o; o >>= 1) v += __shfl_xor_sync(0xffffffffu, v, o);
    return v;
}

// ---------------------------------------------------------------------------
// Fused v3+v2: grid 32, block 256. Each block computes the FULL v3 (w3 is
// small and L2-resident), then its own 32-col chunk of v2 (complete sum).
// Block 0 additionally seeds g_r = pred_b + d2.v3 + d3.pw_h. All blocks
// help zero g_u.
__global__ __launch_bounds__(256) void k_a(
    const float* __restrict__ w3, const float* __restrict__ bn3,
    const float* __restrict__ b3,
    const float* __restrict__ w2, const float* __restrict__ bn2,
    const float* __restrict__ b2,
    const float* __restrict__ pred_w, const float* __restrict__ pred_b) {

    __shared__ float t3[H3];     // a3 .* pw_h
    __shared__ float s2[H2];     // a2 .* v3
    __shared__ float part[8][32];
    __shared__ float redv[8];

    const int t   = threadIdx.x;
    const int bid = blockIdx.x;

    // zero g_u (32 blocks x 256 = 8192 >= 1792)
    int gt = bid * 256 + t;
    if (gt < 1792) g_u[gt] = 0.f;

    // t3
    {
        float a3 = bn3[t] * rsqrtf(bn3[3 * H3 + t] + EPSF);
        t3[t] = a3 * pred_w[D0 + t];
    }
    __syncthreads();

    // full v3: each thread 2 columns
    float v3a = 0.f, v3b = 0.f;
    {
        int j0 = t, j1 = t + 256;
        for (int i = 0; i < H3; i++) {
            float w = t3[i];
            v3a += w3[i * H2 + j0] * w;
            v3b += w3[i * H2 + j1] * w;
        }
    }
    // a2 .* v3 into s2; block 0 accumulates d2.v3
    float rloc = 0.f;
    {
        int j0 = t, j1 = t + 256;
        float a2a = bn2[j0] * rsqrtf(bn2[3 * H2 + j0] + EPSF);
        float a2b = bn2[j1] * rsqrtf(bn2[3 * H2 + j1] + EPSF);
        s2[j0] = a2a * v3a;
        s2[j1] = a2b * v3b;
        if (bid == 0) {
            rloc += (a2a * b2[j0] + bn2[H2 + j0] - bn2[2 * H2 + j0] * a2a) * v3a;
            rloc += (a2b * b2[j1] + bn2[H2 + j1] - bn2[2 * H2 + j1] * a2b) * v3b;
            // d3 . pw_h
            float a3 = bn3[t] * rsqrtf(bn3[3 * H3 + t] + EPSF);
            rloc += (a3 * b3[t] + bn3[H3 + t] - bn3[2 * H3 + t] * a3) * pred_w[D0 + t];
        }
    }
    __syncthreads();

    // v2 chunk: 32 cols per block; 8 threads per col over i-halves of 64
    {
        int jc  = t & 31;              // col within chunk
        int seg = t >> 5;              // 0..7 i-segment
        int j   = bid * 32 + jc;
        float acc = 0.f;
        int i0 = seg * 64;
        #pragma unroll 8
        for (int i = 0; i < 64; i++)
            acc += w2[(i0 + i) * H1 + j] * s2[i0 + i];
        part[seg][jc] = acc;
    }
    __syncthreads();
    if (t < 32) {
        float v = 0.f;
        #pragma unroll
        for (int s = 0; s < 8; s++) v += part[s][t];
        g_v2[bid * 32 + t] = v;
    }

    if (bid == 0) {
        rloc = warp_sum(rloc);
        if ((t & 31) == 0) redv[t >> 5] = rloc;
        __syncthreads();
        if (t == 0) {
            float rb = pred_b[0];
            #pragma unroll
            for (int w = 0; w < 8; w++) rb += redv[w];
            g_r = rb;
        }
    }
}

// ---------------------------------------------------------------------------
// u: grid 224 = ib(32, chunk 32) x jb(7, 256 cols), block 256.
// Reads full g_v2; atomicAdds u partials and r contributions.
__global__ __launch_bounds__(256) void k_u(
    const float* __restrict__ w1, const float* __restrict__ bn1,
    const float* __restrict__ b1, const float* __restrict__ bn0) {
    int bid = blockIdx.x;
    int jb = bid % 7, ib = bid / 7;
    int t = threadIdx.x;
    int i0 = ib * 32;
    __shared__ float ts[32];
    __shared__ float red[8];
    float rloc = 0.f;

    if (t < 32) {
        int i = i0 + t;
        float v2 = g_v2[i];
        float a1 = bn1[i] * rsqrtf(bn1[3 * H1 + i] + EPSF);
        ts[t] = a1 * v2;
        if (jb == 0)
            rloc += (a1 * b1[i] + bn1[H1 + i] - bn1[2 * H1 + i] * a1) * v2;
    }
    __syncthreads();

    int j = jb * 256 + t;
    if (j < INW) {
        float acc = 0.f;
        #pragma unroll 8
        for (int i = 0; i < 32; i++)
            acc += w1[(size_t)(i0 + i) * INW + j] * ts[i];
        atomicAdd(&g_u[j], acc);
        float a0 = bn0[j] * rsqrtf(bn0[3 * INW + j] + EPSF);
        float c0 = bn0[INW + j] - bn0[2 * INW + j] * a0;
        rloc += c0 * acc;
    }

    rloc = warp_sum(rloc);
    if ((t & 31) == 0) red[t >> 5] = rloc;
    __syncthreads();
    if (t == 0) {
        float rb = 0.f;
        #pragma unroll
        for (int w = 0; w < 8; w++) rb += red[w];
        atomicAdd(&g_r, rb);
    }
}

// ---------------------------------------------------------------------------
// Main gather kernel: 256 thr (8 warps), 2 rows/warp, grid 256,
// launch_bounds(256,4) -> 64 regs, 32 warps/SM. float2 loads, depth-5
// dual-row prefetch. Coefficient LDS loads serve both rows.
__global__ __launch_bounds__(256, 4) void k_main(
    const float* __restrict__ numb, const int* __restrict__ cat,
    const float* __restrict__ emb,  const float* __restrict__ cross_w,
    const float* __restrict__ cross_b, const float* __restrict__ pred_w,
    const float* __restrict__ bn0, float* __restrict__ out) {

    __shared__ float2 sv0[832], sv1[832], sv2[832], sv3[832], sv4[832];
    __shared__ float  s_qn[16];
    __shared__ float  redm[3][8];
    __shared__ float  s_sc[4];

    const int tid  = threadIdx.x;
    const int warp = tid >> 5;
    const int lane = tid & 31;
    const int rowA = blockIdx.x * 16 + warp * 2;
    const int rowB = rowA + 1;

    int miA = (lane < Fn) ? cat[rowA * Fn + lane] : 0;
    int miB = (lane < Fn) ? cat[rowB * Fn + lane] : 0;

    // ---- prologue: staging, q from g_u, Sc sums ----
    float p1 = 0.f, p2 = 0.f, p3 = 0.f;
    {
        const float2* cwp = (const float2*)cross_w;
        const float2* pwp = (const float2*)pred_w;
        #pragma unroll
        for (int k = tid; k < 832; k += 256) {
            float2 c0 = cwp[k];
            float2 c1 = cwp[832 + k];
            float2 c2 = cwp[1664 + k];
            float2 pw = pwp[k];
            sv0[k] = c0; sv1[k] = c1; sv2[k] = c2; sv3[k] = pw;
            p1 += c1.x + c1.y; p2 += c2.x + c2.y; p3 += pw.x + pw.y;
        }
        float* sv4f = (float*)sv4;
        #pragma unroll
        for (int j = tid; j < INW; j += 256) {
            float a0 = bn0[j] * rsqrtf(bn0[3 * INW + j] + EPSF);
            float q = a0 * g_u[j];
            if (j < D0) sv4f[j] = q;
            else        s_qn[j - D0] = q;
        }
        if (tid == 0) s_sc[3] = g_r;
    }
    p1 = warp_sum(p1); p2 = warp_sum(p2); p3 = warp_sum(p3);
    if (lane == 0) { redm[0][warp] = p1; redm[1][warp] = p2; redm[2][warp] = p3; }
    __syncthreads();
    if (tid < 32) {
        float a = (tid < 8) ? redm[0][tid] : 0.f;
        float b = (tid < 8) ? redm[1][tid] : 0.f;
        float c = (tid < 8) ? redm[2][tid] : 0.f;
        a = warp_sum(a); b = warp_sum(b); c = warp_sum(c);
        if (tid == 0) { s_sc[0] = a; s_sc[1] = b; s_sc[2] = c; }
    }
    __syncthreads();

    // ---- gather: depth-5 dual-row prefetch, 26 features ----
    float a0A = 0.f, a1A = 0.f, a2A = 0.f, a3A = 0.f, a4A = 0.f;
    float a0B = 0.f, a1B = 0.f, a2B = 0.f, a3B = 0.f, a4B = 0.f;

    #define EMB_LD(MI, F) \
        __ldg(reinterpret_cast<const float2*>(emb + (size_t)(F) * (Vn * Dn)) \
              + (size_t)__shfl_sync(0xffffffffu, (MI), (F)) * 32 + lane)

    float2 eA[5], eB[5];
    #pragma unroll
    for (int d = 0; d < 5; d++) { eA[d] = EMB_LD(miA, d); eB[d] = EMB_LD(miB, d); }

    #pragma unroll
    for (int f = 0; f < Fn; f++) {
        float2 evA = eA[f % 5];
        float2 evB = eB[f % 5];
        if (f + 5 < Fn) {
            eA[f % 5] = EMB_LD(miA, f + 5);
            eB[f % 5] = EMB_LD(miB, f + 5);
        }
        int b = f * 32 + lane;
        float2 c;
        c = sv0[b]; a0A += evA.x*c.x + evA.y*c.y; a0B += evB.x*c.x + evB.y*c.y;
        c = sv1[b]; a1A += evA.x*c.x + evA.y*c.y; a1B += evB.x*c.x + evB.y*c.y;
        c = sv2[b]; a2A += evA.x*c.x + evA.y*c.y; a2B += evB.x*c.x + evB.y*c.y;
        c = sv3[b]; a3A += evA.x*c.x + evA.y*c.y; a3B += evB.x*c.x + evB.y*c.y;
        c = sv4[b]; a4A += evA.x*c.x + evA.y*c.y; a4B += evB.x*c.x + evB.y*c.y;
    }
    #undef EMB_LD

    if (lane < NUMB)
        a4A += numb[rowA * NUMB + lane] * s_qn[lane];
    else if (lane >= 16 && lane < 16 + NUMB)
        a4B += numb[rowB * NUMB + (lane - 16)] * s_qn[lane - 16];

    a0A = warp_sum(a0A); a1A = warp_sum(a1A); a2A = warp_sum(a2A);
    a3A = warp_sum(a3A); a4A = warp_sum(a4A);
    a0B = warp_sum(a0B); a1B = warp_sum(a1B); a2B = warp_sum(a2B);
    a3B = warp_sum(a3B); a4B = warp_sum(a4B);

    if (lane < 2) {
        float d0 = (lane == 0) ? a0A : a0B;
        float d1 = (lane == 0) ? a1A : a1B;
        float d2 = (lane == 0) ? a2A : a2B;
        float d3 = (lane == 0) ? a3A : a3B;
        float d4 = (lane == 0) ? a4A : a4B;
        int   rw = (lane == 0) ? rowA : rowB;

        float cb0 = cross_b[0], cb1 = cross_b[1], cb2 = cross_b[2];
        float Sc1 = s_sc[0], Sc2 = s_sc[1], Sp = s_sc[2], rtot = s_sc[3];

        float al = d0 + 1.f;
        float be = cb0;
        float sd1 = al * d1 + be * Sc1;
        al = (sd1 + 1.f) * al;
        be = (sd1 + 1.f) * be + cb1;
        float sd2 = al * d2 + be * Sc2;
        al = (sd2 + 1.f) * al;
        be = (sd2 + 1.f) * be + cb2;

        float z = al * d3 + be * Sp + d4 + rtot;
        out[rw] = 1.f / (1.f + expf(-z));
    }
}

// ---------------------------------------------------------------------------
extern "C" void kernel_launch(void* const* d_in, const int* in_sizes, int n_in,
                              void* d_out, int out_size) {
    const float* numb    = (const float*)d_in[0];
    const int*   cat     = (const int*)  d_in[1];
    const float* emb     = (const float*)d_in[2];
    const float* bn0     = (const float*)d_in[3];
    const float* w1      = (const float*)d_in[4];
    const float* b1      = (const float*)d_in[5];
    const float* bn1     = (const float*)d_in[6];
    const float* w2      = (const float*)d_in[7];
    const float* b2      = (const float*)d_in[8];
    const float* bn2     = (const float*)d_in[9];
    const float* w3      = (const float*)d_in[10];
    const float* b3      = (const float*)d_in[11];
    const float* bn3     = (const float*)d_in[12];
    const float* cross_w = (const float*)d_in[13];
    const float* cross_b = (const float*)d_in[14];
    const float* pred_w  = (const float*)d_in[15];
    const float* pred_b  = (const float*)d_in[16];
    float* out = (float*)d_out;

    k_a<<<32, 256>>>(w3, bn3, b3, w2, bn2, b2, pred_w, pred_b);
    k_u<<<224, 256>>>(w1, bn1, b1, bn0);
    k_main<<<256, 256>>>(numb, cat, emb, cross_w, cross_b, pred_w, bn0, out);
}

// round 10
// speedup vs baseline: 1.4133x; 1.4133x over previous
#include <cuda_runtime.h>
#include <math.h>

// DCN collapsed-affine, round 10: R8's proven chain + R9's k_main design.

#define EPSF 1e-5f

constexpr int Bn   = 4096;
constexpr int Fn   = 26;
constexpr int Vn   = 10000;
constexpr int Dn   = 64;
constexpr int D0   = 1664;   // Fn*Dn
constexpr int NUMB = 13;
constexpr int INW  = 1677;   // D0 + NUMB
constexpr int H1   = 1024;
constexpr int H2   = 512;
constexpr int H3   = 256;

// Scratch (device globals)
__device__ float g_v3p[16][H2];
__device__ float g_v2p[16][H1];
__device__ float g_u[1792];
__device__ float g_r;

__device__ __forceinline__ float warp_sum(float v) {
    #pragma unroll
    for (int o = 16; o; o >>= 1) v += __shfl_xor_sync(0xffffffffu, v, o);
    return v;
}

// ---------------------------------------------------------------------------
__global__ __launch_bounds__(256) void k_v3(
    const float* __restrict__ w3, const float* __restrict__ bn3,
    const float* __restrict__ pred_w, const float* __restrict__ pred_b) {
    int bid = blockIdx.x;
    int ib = bid >> 1, jb = bid & 1;
    int t = threadIdx.x;
    int i0 = ib * 16;
    __shared__ float ts[16];
    if (t < 16) {
        int i = i0 + t;
        float a3 = bn3[i] * rsqrtf(bn3[3 * H3 + i] + EPSF);
        ts[t] = a3 * pred_w[D0 + i];
    }
    int gt = bid * 256 + t;
    if (gt < 1792) g_u[gt] = 0.f;
    if (gt == 0) g_r = pred_b[0];
    __syncthreads();
    int j = jb * 256 + t;
    float acc = 0.f;
    #pragma unroll
    for (int i = 0; i < 16; i++) acc += w3[(i0 + i) * H2 + j] * ts[i];
    g_v3p[ib][j] = acc;
}

// ---------------------------------------------------------------------------
__global__ __launch_bounds__(128) void k_v2(
    const float* __restrict__ w2, const float* __restrict__ bn2,
    const float* __restrict__ b2, const float* __restrict__ bn3,
    const float* __restrict__ b3, const float* __restrict__ pred_w) {
    int bid = blockIdx.x;
    int jb = bid & 7, ib = bid >> 3;
    int t = threadIdx.x;
    int i0 = ib * 32;
    __shared__ float ts[32];
    __shared__ float red[4];
    float rloc = 0.f;

    if (t < 32) {
        int i = i0 + t;
        float v3 = 0.f;
        #pragma unroll
        for (int p = 0; p < 16; p++) v3 += g_v3p[p][i];
        float a2 = bn2[i] * rsqrtf(bn2[3 * H2 + i] + EPSF);
        ts[t] = a2 * v3;
        if (jb == 0)
            rloc += (a2 * b2[i] + bn2[H2 + i] - bn2[2 * H2 + i] * a2) * v3;
    }
    if (bid == 0) {
        #pragma unroll
        for (int i = t; i < H3; i += 128) {
            float a3 = bn3[i] * rsqrtf(bn3[3 * H3 + i] + EPSF);
            rloc += (a3 * b3[i] + bn3[H3 + i] - bn3[2 * H3 + i] * a3) * pred_w[D0 + i];
        }
    }
    __syncthreads();

    int j = jb * 128 + t;
    float acc = 0.f;
    #pragma unroll 8
    for (int i = 0; i < 32; i++) acc += w2[(i0 + i) * H1 + j] * ts[i];
    g_v2p[ib][j] = acc;

    if (jb == 0) {
        rloc = warp_sum(rloc);
        if ((t & 31) == 0) red[t >> 5] = rloc;
        __syncthreads();
        if (t == 0) atomicAdd(&g_r, red[0] + red[1] + red[2] + red[3]);
    }
}

// ---------------------------------------------------------------------------
// u: grid 224 = ib(32, chunk 32) x jb(7, 256 cols), block 256.
__global__ __launch_bounds__(256) void k_u(
    const float* __restrict__ w1, const float* __restrict__ bn1,
    const float* __restrict__ b1, const float* __restrict__ bn0) {
    int bid = blockIdx.x;
    int jb = bid % 7, ib = bid / 7;
    int t = threadIdx.x;
    int i0 = ib * 32;
    __shared__ float ts[32];
    __shared__ float red[8];
    float rloc = 0.f;

    if (t < 32) {
        int i = i0 + t;
        float v2 = 0.f;
        #pragma unroll
        for (int p = 0; p < 16; p++) v2 += g_v2p[p][i];
        float a1 = bn1[i] * rsqrtf(bn1[3 * H1 + i] + EPSF);
        ts[t] = a1 * v2;
        if (jb == 0)
            rloc += (a1 * b1[i] + bn1[H1 + i] - bn1[2 * H1 + i] * a1) * v2;
    }
    __syncthreads();

    int j = jb * 256 + t;
    if (j < INW) {
        float acc = 0.f;
        #pragma unroll 8
        for (int i = 0; i < 32; i++)
            acc += w1[(size_t)(i0 + i) * INW + j] * ts[i];
        atomicAdd(&g_u[j], acc);
        float a0 = bn0[j] * rsqrtf(bn0[3 * INW + j] + EPSF);
        float c0 = bn0[INW + j] - bn0[2 * INW + j] * a0;
        rloc += c0 * acc;
    }

    rloc = warp_sum(rloc);
    if ((t & 31) == 0) red[t >> 5] = rloc;
    __syncthreads();
    if (t == 0) {
        float rb = 0.f;
        #pragma unroll
        for (int w = 0; w < 8; w++) rb += red[w];
        atomicAdd(&g_r, rb);
    }
}

// ---------------------------------------------------------------------------
// Main gather kernel: 256 thr (8 warps), 2 rows/warp, grid 256,
// launch_bounds(256,4) -> 64 regs, 32 warps/SM. float2 loads, depth-5
// dual-row prefetch. Coefficient LDS loads serve both rows.
__global__ __launch_bounds__(256, 4) void k_main(
    const float* __restrict__ numb, const int* __restrict__ cat,
    const float* __restrict__ emb,  const float* __restrict__ cross_w,
    const float* __restrict__ cross_b, const float* __restrict__ pred_w,
    const float* __restrict__ bn0, float* __restrict__ out) {

    __shared__ float2 sv0[832], sv1[832], sv2[832], sv3[832], sv4[832];
    __shared__ float  s_qn[16];
    __shared__ float  redm[3][8];
    __shared__ float  s_sc[4];

    const int tid  = threadIdx.x;
    const int warp = tid >> 5;
    const int lane = tid & 31;
    const int rowA = blockIdx.x * 16 + warp * 2;
    const int rowB = rowA + 1;

    int miA = (lane < Fn) ? cat[rowA * Fn + lane] : 0;
    int miB = (lane < Fn) ? cat[rowB * Fn + lane] : 0;

    // ---- prologue: staging, q from g_u, Sc sums ----
    float p1 = 0.f, p2 = 0.f, p3 = 0.f;
    {
        const float2* cwp = (const float2*)cross_w;
        const float2* pwp = (const float2*)pred_w;
        #pragma unroll
        for (int k = tid; k < 832; k += 256) {
            float2 c0 = cwp[k];
            float2 c1 = cwp[832 + k];
            float2 c2 = cwp[1664 + k];
            float2 pw = pwp[k];
            sv0[k] = c0; sv1[k] = c1; sv2[k] = c2; sv3[k] = pw;
            p1 += c1.x + c1.y; p2 += c2.x + c2.y; p3 += pw.x + pw.y;
        }
        float* sv4f = (float*)sv4;
        #pragma unroll
        for (int j = tid; j < INW; j += 256) {
            float a0 = bn0[j] * rsqrtf(bn0[3 * INW + j] + EPSF);
            float q = a0 * g_u[j];
            if (j < D0) sv4f[j] = q;
            else        s_qn[j - D0] = q;
        }
        if (tid == 0) s_sc[3] = g_r;
    }
    p1 = warp_sum(p1); p2 = warp_sum(p2); p3 = warp_sum(p3);
    if (lane == 0) { redm[0][warp] = p1; redm[1][warp] = p2; redm[2][warp] = p3; }
    __syncthreads();
    if (tid < 32) {
        float a = (tid < 8) ? redm[0][tid] : 0.f;
        float b = (tid < 8) ? redm[1][tid] : 0.f;
        float c = (tid < 8) ? redm[2][tid] : 0.f;
        a = warp_sum(a); b = warp_sum(b); c = warp_sum(c);
        if (tid == 0) { s_sc[0] = a; s_sc[1] = b; s_sc[2] = c; }
    }
    __syncthreads();

    // ---- gather: depth-5 dual-row prefetch, 26 features ----
    float a0A = 0.f, a1A = 0.f, a2A = 0.f, a3A = 0.f, a4A = 0.f;
    float a0B = 0.f, a1B = 0.f, a2B = 0.f, a3B = 0.f, a4B = 0.f;

    #define EMB_LD(MI, F) \
        __ldg(reinterpret_cast<const float2*>(emb + (size_t)(F) * (Vn * Dn)) \
              + (size_t)__shfl_sync(0xffffffffu, (MI), (F)) * 32 + lane)

    float2 eA[5], eB[5];
    #pragma unroll
    for (int d = 0; d < 5; d++) { eA[d] = EMB_LD(miA, d); eB[d] = EMB_LD(miB, d); }

    #pragma unroll
    for (int f = 0; f < Fn; f++) {
        float2 evA = eA[f % 5];
        float2 evB = eB[f % 5];
        if (f + 5 < Fn) {
            eA[f % 5] = EMB_LD(miA, f + 5);
            eB[f % 5] = EMB_LD(miB, f + 5);
        }
        int b = f * 32 + lane;
        float2 c;
        c = sv0[b]; a0A += evA.x*c.x + evA.y*c.y; a0B += evB.x*c.x + evB.y*c.y;
        c = sv1[b]; a1A += evA.x*c.x + evA.y*c.y; a1B += evB.x*c.x + evB.y*c.y;
        c = sv2[b]; a2A += evA.x*c.x + evA.y*c.y; a2B += evB.x*c.x + evB.y*c.y;
        c = sv3[b]; a3A += evA.x*c.x + evA.y*c.y; a3B += evB.x*c.x + evB.y*c.y;
        c = sv4[b]; a4A += evA.x*c.x + evA.y*c.y; a4B += evB.x*c.x + evB.y*c.y;
    }
    #undef EMB_LD

    if (lane < NUMB)
        a4A += numb[rowA * NUMB + lane] * s_qn[lane];
    else if (lane >= 16 && lane < 16 + NUMB)
        a4B += numb[rowB * NUMB + (lane - 16)] * s_qn[lane - 16];

    a0A = warp_sum(a0A); a1A = warp_sum(a1A); a2A = warp_sum(a2A);
    a3A = warp_sum(a3A); a4A = warp_sum(a4A);
    a0B = warp_sum(a0B); a1B = warp_sum(a1B); a2B = warp_sum(a2B);
    a3B = warp_sum(a3B); a4B = warp_sum(a4B);

    if (lane < 2) {
        float d0 = (lane == 0) ? a0A : a0B;
        float d1 = (lane == 0) ? a1A : a1B;
        float d2 = (lane == 0) ? a2A : a2B;
        float d3 = (lane == 0) ? a3A : a3B;
        float d4 = (lane == 0) ? a4A : a4B;
        int   rw = (lane == 0) ? rowA : rowB;

        float cb0 = cross_b[0], cb1 = cross_b[1], cb2 = cross_b[2];
        float Sc1 = s_sc[0], Sc2 = s_sc[1], Sp = s_sc[2], rtot = s_sc[3];

        float al = d0 + 1.f;
        float be = cb0;
        float sd1 = al * d1 + be * Sc1;
        al = (sd1 + 1.f) * al;
        be = (sd1 + 1.f) * be + cb1;
        float sd2 = al * d2 + be * Sc2;
        al = (sd2 + 1.f) * al;
        be = (sd2 + 1.f) * be + cb2;

        float z = al * d3 + be * Sp + d4 + rtot;
        out[rw] = 1.f / (1.f + expf(-z));
    }
}

// ---------------------------------------------------------------------------
extern "C" void kernel_launch(void* const* d_in, const int* in_sizes, int n_in,
                              void* d_out, int out_size) {
    const float* numb    = (const float*)d_in[0];
    const int*   cat     = (const int*)  d_in[1];
    const float* emb     = (const float*)d_in[2];
    const float* bn0     = (const float*)d_in[3];
    const float* w1      = (const float*)d_in[4];
    const float* b1      = (const float*)d_in[5];
    const float* bn1     = (const float*)d_in[6];
    const float* w2      = (const float*)d_in[7];
    const float* b2      = (const float*)d_in[8];
    const float* bn2     = (const float*)d_in[9];
    const float* w3      = (const float*)d_in[10];
    const float* b3      = (const float*)d_in[11];
    const float* bn3     = (const float*)d_in[12];
    const float* cross_w = (const float*)d_in[13];
    const float* cross_b = (const float*)d_in[14];
    const float* pred_w  = (const float*)d_in[15];
    const float* pred_b  = (const float*)d_in[16];
    float* out = (float*)d_out;

    k_v3<<<32, 256>>>(w3, bn3, pred_w, pred_b);
    k_v2<<<128, 128>>>(w2, bn2, b2, bn3, b3, pred_w);
    k_u<<<224, 256>>>(w1, bn1, b1, bn0);
    k_main<<<256, 256>>>(numb, cat, emb, cross_w, cross_b, pred_w, bn0, out);
}